// round 5
// baseline (speedup 1.0000x reference)
#include <cuda_runtime.h>
#include <cstdint>

// ---------------------------------------------------------------------------
// SpikingOpticalFlowBranch
//   flow[t] = x[t+1]-x[t]                      t in [0,19)
//   u = conv3x3(flow, w_conv) + b_conv         (SAME, NHWC, 2->64)
//   V = beta*V + u ; s = (V > 1) ; V -= s      (LIF scan over t, V carried)
//   logits[t,b,:] = mean_{h,w}(s) @ w_head + b_head
//   readout = mean_t logits ; sr = mean(all s)
//
// Strategy: one thread per pixel carries V[64] in registers across all 19
// steps (u never touches global memory). Spike counts reduced via warp
// ballots -> shared -> global int atomics into g_chsum[t][b][ch]; two tiny
// epilogue kernels build the 3201-float output.
// Output layout: [0,160) readout, [160,3200) logits (t-major), [3200] sr.
// ---------------------------------------------------------------------------

#define T_STEPS 19
#define BATCH   16
#define HH      128
#define WW      128
#define NCH     64
#define OUTD    10
#define TILE    16
#define BETA_F  0.9f
#define THR_F   1.0f

// halo tile: 18x18 pixels x 2 input channels
#define HALO    18
#define FRAME_ELEMS (HALO*HALO*2)   // 648

__device__ int g_chsum[T_STEPS * BATCH * NCH];   // spike counts per (t,b,ch)

// ---------------------------------------------------------------------------
__global__ void zero_chsum_kernel() {
    int i = blockIdx.x * blockDim.x + threadIdx.x;
    if (i < T_STEPS * BATCH * NCH) g_chsum[i] = 0;
}

// ---------------------------------------------------------------------------
// Main fused kernel: grid = BATCH * (8x8 tiles) = 1024 blocks, 256 threads.
// Each thread owns one pixel, all 64 channels of V in registers.
// ---------------------------------------------------------------------------
__global__ __launch_bounds__(256)
void lif_main_kernel(const float* __restrict__ x,
                     const float* __restrict__ wconv,
                     const float* __restrict__ bconv) {
    __shared__ float  frame_s[2][FRAME_ELEMS];   // ping-pong raw frames
    __shared__ float  flow_s[FRAME_ELEMS];       // current flow tile
    __shared__ float4 ws4[18 * 16];              // weights [tap][ch], tap=(ky*3+kx)*2+ci
    __shared__ float4 bs4[16];                   // bias
    __shared__ int    chsum_s[NCH];

    const int tid  = threadIdx.x;
    const int lane = tid & 31;
    const int b    = blockIdx.x >> 6;            // batch
    const int tile = blockIdx.x & 63;
    const int th0  = (tile >> 3) << 4;           // tile origin
    const int tw0  = (tile & 7) << 4;
    const int ty   = tid >> 4;
    const int tx   = tid & 15;

    // ---- load weights/bias once (global layout [ky][kx][ci][co] == [tap][co]) ----
    {
        float* wsf = reinterpret_cast<float*>(ws4);
        for (int i = tid; i < 18 * NCH; i += 256) wsf[i] = wconv[i];
        if (tid < NCH) reinterpret_cast<float*>(bs4)[tid] = bconv[tid];
    }

    // ---- frame loader with zero padding (SAME conv => flow=0 outside) ----
    auto load_frame = [&](int t, float* dst) {
        const float* xt = x + ((size_t)t * BATCH + b) * (HH * WW * 2);
        for (int i = tid; i < FRAME_ELEMS; i += 256) {
            int row = i / (HALO * 2);
            int rem = i - row * (HALO * 2);
            int col = rem >> 1;
            int c   = rem & 1;
            int gh  = th0 + row - 1;
            int gw  = tw0 + col - 1;
            float v = 0.0f;
            if ((unsigned)gh < (unsigned)HH && (unsigned)gw < (unsigned)WW)
                v = xt[(gh * WW + gw) * 2 + c];
            dst[i] = v;
        }
    };

    load_frame(0, frame_s[0]);

    float V[NCH];
#pragma unroll
    for (int ch = 0; ch < NCH; ch++) V[ch] = 0.0f;

#pragma unroll 1
    for (int t = 0; t < T_STEPS; t++) {
        // phase A: zero per-block counters + stage next frame
        if (tid < NCH) chsum_s[tid] = 0;
        load_frame(t + 1, frame_s[(t + 1) & 1]);
        __syncthreads();

        // phase B: flow tile = frame[t+1] - frame[t]
        {
            const float* fc = frame_s[(t + 1) & 1];
            const float* fp = frame_s[t & 1];
            for (int i = tid; i < FRAME_ELEMS; i += 256) flow_s[i] = fc[i] - fp[i];
        }
        __syncthreads();

        // phase C: conv + LIF for this pixel, all 64 channels
        float f[18];
#pragma unroll
        for (int dy = 0; dy < 3; dy++)
#pragma unroll
            for (int dx = 0; dx < 3; dx++) {
                int base = ((ty + dy) * HALO + (tx + dx)) * 2;
                f[(dy * 3 + dx) * 2 + 0] = flow_s[base + 0];
                f[(dy * 3 + dx) * 2 + 1] = flow_s[base + 1];
            }

        // V = beta*V + bias
#pragma unroll
        for (int c4 = 0; c4 < 16; c4++) {
            float4 bb = bs4[c4];
            V[c4 * 4 + 0] = BETA_F * V[c4 * 4 + 0] + bb.x;
            V[c4 * 4 + 1] = BETA_F * V[c4 * 4 + 1] + bb.y;
            V[c4 * 4 + 2] = BETA_F * V[c4 * 4 + 2] + bb.z;
            V[c4 * 4 + 3] = BETA_F * V[c4 * 4 + 3] + bb.w;
        }
        // V += sum_taps f[tap] * w[tap][ch]   (float4 broadcast loads)
#pragma unroll
        for (int tap = 0; tap < 18; tap++) {
            float fv = f[tap];
#pragma unroll
            for (int c4 = 0; c4 < 16; c4++) {
                float4 w = ws4[tap * 16 + c4];
                V[c4 * 4 + 0] += fv * w.x;
                V[c4 * 4 + 1] += fv * w.y;
                V[c4 * 4 + 2] += fv * w.z;
                V[c4 * 4 + 3] += fv * w.w;
            }
        }

        // spike + soft reset + warp-ballot spike counting
        int acc0 = 0, acc1 = 0;
#pragma unroll
        for (int ch = 0; ch < NCH; ch++) {
            bool s = V[ch] > THR_F;               // strict >, matches (u > 0)
            unsigned m = __ballot_sync(0xffffffffu, s);
            if (s) V[ch] -= THR_F;
            if (ch < 32) { if (lane == ch)        acc0 += __popc(m); }
            else         { if (lane == (ch - 32)) acc1 += __popc(m); }
        }
        atomicAdd(&chsum_s[lane],      acc0);
        atomicAdd(&chsum_s[lane + 32], acc1);
        __syncthreads();

        // phase D: flush to global
        if (tid < NCH)
            atomicAdd(&g_chsum[(t * BATCH + b) * NCH + tid], chsum_s[tid]);
        // (next iter: same thread re-zeros chsum_s[tid] after two barriers)
    }
}

// ---------------------------------------------------------------------------
// Epilogue 1: logits[t][b][o] = (chsum/16384) @ w_head + b_head
// ---------------------------------------------------------------------------
__global__ void logits_kernel(const float* __restrict__ w_head,
                              const float* __restrict__ b_head,
                              float* __restrict__ out) {
    int idx = blockIdx.x * blockDim.x + threadIdx.x;   // (t*16 + b)
    if (idx >= T_STEPS * BATCH) return;
    const int* cs = g_chsum + idx * NCH;
    float acc[OUTD];
#pragma unroll
    for (int o = 0; o < OUTD; o++) acc[o] = b_head[o];
    for (int ch = 0; ch < NCH; ch++) {
        float ms = (float)cs[ch] * (1.0f / 16384.0f);  // exact: /2^14
#pragma unroll
        for (int o = 0; o < OUTD; o++) acc[o] += ms * w_head[ch * OUTD + o];
    }
#pragma unroll
    for (int o = 0; o < OUTD; o++) out[160 + idx * OUTD + o] = acc[o];
}

// ---------------------------------------------------------------------------
// Epilogue 2: readout = mean_t logits; sr = total spikes / (19*16*128*128*64)
// ---------------------------------------------------------------------------
__global__ void final_kernel(float* __restrict__ out) {
    __shared__ long long part[256];
    int tid = threadIdx.x;

    if (tid < BATCH * OUTD) {
        int b = tid / OUTD, o = tid % OUTD;
        float s = 0.0f;
        for (int t = 0; t < T_STEPS; t++)
            s += out[160 + (t * BATCH + b) * OUTD + o];
        out[b * OUTD + o] = s * (1.0f / (float)T_STEPS);
    }

    long long tot = 0;
    for (int i = tid; i < T_STEPS * BATCH * NCH; i += 256) tot += (long long)g_chsum[i];
    part[tid] = tot;
    __syncthreads();
    for (int s = 128; s > 0; s >>= 1) {
        if (tid < s) part[tid] += part[tid + s];
        __syncthreads();
    }
    if (tid == 0)
        out[3200] = (float)((double)part[0] / 318767104.0);  // 19*16*128*128*64
}

// ---------------------------------------------------------------------------
extern "C" void kernel_launch(void* const* d_in, const int* in_sizes, int n_in,
                              void* d_out, int out_size) {
    const float* x     = (const float*)d_in[0];   // [20,16,128,128,2]
    const float* wconv = (const float*)d_in[1];   // [3,3,2,64]
    const float* bconv = (const float*)d_in[2];   // [64]
    const float* whead = (const float*)d_in[3];   // [64,10]
    const float* bhead = (const float*)d_in[4];   // [10]
    float* out = (float*)d_out;                   // 3201 floats

    zero_chsum_kernel<<<76, 256>>>();             // 76*256 = 19456
    lif_main_kernel<<<BATCH * 64, 256>>>(x, wconv, bconv);
    logits_kernel<<<1, 320>>>(whead, bhead, out);
    final_kernel<<<1, 256>>>(out);
}